// round 1
// baseline (speedup 1.0000x reference)
#include <cuda_runtime.h>
#include <math.h>

#define VOCAB 50257
#define DIM   128
#define HID   128
#define GATES 512
#define BATCH 64
#define SEQ   2048

// Projected embedding table: P[v][g] = dot(emb[v], W_ih[g]) + b_ih[g] + b_hh[g]
__device__ float g_P[(size_t)VOCAB * GATES];

// ---------------------------------------------------------------------------
// Kernel 1: P = emb @ W_ih^T + b   (3.3 GMAC fp32 SGEMM, K=128 resident)
// Block: 256 threads computes a 64x64 tile. Full K loaded to SMEM once.
// ---------------------------------------------------------------------------
__global__ __launch_bounds__(256) void proj_kernel(
    const float* __restrict__ emb,
    const float* __restrict__ W_ih,
    const float* __restrict__ b_ih,
    const float* __restrict__ b_hh)
{
    extern __shared__ float sm1[];
    float* As = sm1;              // [64][129] vocab rows (padded stride kills bank conflicts)
    float* Bs = sm1 + 64 * 129;   // [64][129] gate rows

    const int tid  = threadIdx.x;
    const int tx   = tid & 15;
    const int ty   = tid >> 4;
    const int row0 = blockIdx.y << 6;
    const int n0   = blockIdx.x << 6;

    // Load tiles (natural [m][k] layout, float4 from global, scalar STS)
    #pragma unroll
    for (int i = 0; i < 8; ++i) {
        int idx = tid + (i << 8);
        int m   = idx >> 5;
        int k4  = (idx & 31) << 2;
        int gm  = row0 + m;
        float4 a = make_float4(0.f, 0.f, 0.f, 0.f);
        if (gm < VOCAB)
            a = *reinterpret_cast<const float4*>(emb + (size_t)gm * DIM + k4);
        As[m * 129 + k4 + 0] = a.x;
        As[m * 129 + k4 + 1] = a.y;
        As[m * 129 + k4 + 2] = a.z;
        As[m * 129 + k4 + 3] = a.w;
        float4 w = *reinterpret_cast<const float4*>(W_ih + (size_t)(n0 + m) * DIM + k4);
        Bs[m * 129 + k4 + 0] = w.x;
        Bs[m * 129 + k4 + 1] = w.y;
        Bs[m * 129 + k4 + 2] = w.z;
        Bs[m * 129 + k4 + 3] = w.w;
    }
    __syncthreads();

    float acc[4][4];
    #pragma unroll
    for (int i = 0; i < 4; ++i)
        #pragma unroll
        for (int jj = 0; jj < 4; ++jj) acc[i][jj] = 0.f;

    const float* ap = As + (ty << 2) * 129;
    const float* bp = Bs + (tx << 2) * 129;

    #pragma unroll 8
    for (int k = 0; k < 128; ++k) {
        float a0 = ap[k], a1 = ap[k + 129], a2 = ap[k + 258], a3 = ap[k + 387];
        float b0 = bp[k], b1 = bp[k + 129], b2 = bp[k + 258], b3 = bp[k + 387];
        acc[0][0] += a0 * b0; acc[0][1] += a0 * b1; acc[0][2] += a0 * b2; acc[0][3] += a0 * b3;
        acc[1][0] += a1 * b0; acc[1][1] += a1 * b1; acc[1][2] += a1 * b2; acc[1][3] += a1 * b3;
        acc[2][0] += a2 * b0; acc[2][1] += a2 * b1; acc[2][2] += a2 * b2; acc[2][3] += a2 * b3;
        acc[3][0] += a3 * b0; acc[3][1] += a3 * b1; acc[3][2] += a3 * b2; acc[3][3] += a3 * b3;
    }

    int gn = n0 + (tx << 2);
    float bb0 = b_ih[gn + 0] + b_hh[gn + 0];
    float bb1 = b_ih[gn + 1] + b_hh[gn + 1];
    float bb2 = b_ih[gn + 2] + b_hh[gn + 2];
    float bb3 = b_ih[gn + 3] + b_hh[gn + 3];

    #pragma unroll
    for (int i = 0; i < 4; ++i) {
        int gm = row0 + (ty << 2) + i;
        if (gm < VOCAB) {
            float4 o = make_float4(acc[i][0] + bb0, acc[i][1] + bb1,
                                   acc[i][2] + bb2, acc[i][3] + bb3);
            *reinterpret_cast<float4*>(g_P + (size_t)gm * GATES + gn) = o;
        }
    }
}

// ---------------------------------------------------------------------------
// Kernel 2: recurrent LSTM. One CTA per batch element, 512 threads,
// thread j owns gate row j. Packed f32x2 FMA. W_hh split:
//   k = 0..63   -> 32 ull (64 regs) per thread
//   k = 64..127 -> SMEM, transposed [kpair][row] for conflict-free LDS.128
// ---------------------------------------------------------------------------
#define FMA2(acc, a, b) \
    asm("fma.rn.f32x2 %0, %1, %2, %0;" : "+l"(acc) : "l"(a), "l"(b))

__global__ __launch_bounds__(512, 1) void lstm_kernel(
    const int*   __restrict__ tokens,
    const float* __restrict__ W_hh,
    float*       __restrict__ out)
{
    extern __shared__ unsigned char smraw[];
    unsigned long long* Wl = (unsigned long long*)smraw;         // 16384 ull = 131072 B
    int*   tok_s = (int*)(smraw + 131072);                       // 2048 ints = 8192 B
    float* h_s   = (float*)(smraw + 131072 + 8192);              // 128 floats (16B aligned)
    float* a_s   = h_s + 128;                                    // 512 floats

    const int j = threadIdx.x;
    const int b = blockIdx.x;
    const unsigned long long* W64 = (const unsigned long long*)W_hh;

    // Second half of W_hh (k=64..127) -> SMEM, layout [q=kpair2][row][slot]
    for (int idx = j; idx < 512 * 32; idx += 512) {
        int row = idx >> 5;
        int kk  = idx & 31;   // float-pair index within second half
        unsigned long long v = W64[(size_t)row * 64 + 32 + kk];
        Wl[(size_t)(kk >> 1) * 1024 + row * 2 + (kk & 1)] = v;
    }

    // First half of W_hh (k=0..63) -> registers (32 x 64-bit pairs)
    unsigned long long wreg[32];
    #pragma unroll
    for (int kk = 0; kk < 32; ++kk)
        wreg[kk] = W64[(size_t)j * 64 + kk];

    for (int idx = j; idx < SEQ; idx += 512)
        tok_s[idx] = tokens[(size_t)b * SEQ + idx];

    if (j < 128) h_s[j] = 0.f;
    __syncthreads();

    const float* Pp = (const float*)g_P;
    float x_cur = __ldg(Pp + (size_t)tok_s[0] * GATES + j);
    float c = 0.f;
    const bool sel_tanh = ((j >> 7) == 2);   // gate order: i, f, g(tanh), o

    for (int t = 0; t < SEQ; ++t) {
        float xg = x_cur;
        if (t + 1 < SEQ)  // prefetch next step's projected input (fully coalesced)
            x_cur = __ldg(Pp + (size_t)tok_s[t + 1] * GATES + j);

        unsigned long long acc0 = 0ull, acc1 = 0ull;
        const ulonglong2* h2 = (const ulonglong2*)h_s;
        const ulonglong2* Wt = (const ulonglong2*)Wl;

        #pragma unroll
        for (int q = 0; q < 16; ++q) {               // k = 0..63, weights in regs
            ulonglong2 hv = h2[q];                   // broadcast LDS.128
            FMA2(acc0, wreg[2 * q],     hv.x);
            FMA2(acc1, wreg[2 * q + 1], hv.y);
        }
        #pragma unroll
        for (int q = 0; q < 16; ++q) {               // k = 64..127, weights in SMEM
            ulonglong2 hv = h2[16 + q];
            ulonglong2 wv = Wt[q * 512 + j];         // conflict-free LDS.128
            FMA2(acc0, wv.x, hv.x);
            FMA2(acc1, wv.y, hv.y);
        }

        float s0, s1, s2, s3;
        asm("mov.b64 {%0,%1}, %2;" : "=f"(s0), "=f"(s1) : "l"(acc0));
        asm("mov.b64 {%0,%1}, %2;" : "=f"(s2), "=f"(s3) : "l"(acc1));
        float g = xg + ((s0 + s1) + (s2 + s3));

        float act = sel_tanh ? tanhf(g) : (1.f / (1.f + expf(-g)));
        a_s[j] = act;
        __syncthreads();

        if (j < 128) {
            float ai = a_s[j], af = a_s[128 + j], ag = a_s[256 + j], ao = a_s[384 + j];
            c = fmaf(af, c, ai * ag);
            h_s[j] = ao * tanhf(c);
        }
        __syncthreads();
    }

    if (j < 128) {
        out[(size_t)b * HID + j] = h_s[j];                        // h  [1,64,128]
        out[(size_t)BATCH * HID + (size_t)b * HID + j] = c;       // c  [1,64,128]
    }
}

// ---------------------------------------------------------------------------
extern "C" void kernel_launch(void* const* d_in, const int* in_sizes, int n_in,
                              void* d_out, int out_size)
{
    const int*   tokens = (const int*)  d_in[0];
    const float* emb    = (const float*)d_in[1];
    const float* W_ih   = (const float*)d_in[2];
    const float* W_hh   = (const float*)d_in[3];
    const float* b_ih   = (const float*)d_in[4];
    const float* b_hh   = (const float*)d_in[5];
    float* out = (float*)d_out;

    const int smem1 = 2 * 64 * 129 * (int)sizeof(float);          // 66048 B
    const int smem2 = 131072 + 8192 + (128 + 512) * (int)sizeof(float); // 141824 B
    cudaFuncSetAttribute(proj_kernel, cudaFuncAttributeMaxDynamicSharedMemorySize, smem1);
    cudaFuncSetAttribute(lstm_kernel, cudaFuncAttributeMaxDynamicSharedMemorySize, smem2);

    dim3 g1(GATES / 64, (VOCAB + 63) / 64);
    proj_kernel<<<g1, 256, smem1>>>(emb, W_ih, b_ih, b_hh);
    lstm_kernel<<<BATCH, 512, smem2>>>(tokens, W_hh, out);
}

// round 2
// speedup vs baseline: 1.8159x; 1.8159x over previous
#include <cuda_runtime.h>
#include <math.h>

#define VOCAB 50257
#define DIM   128
#define HID   128
#define GATES 512
#define BATCH 64
#define SEQ   2048

// Projected embedding table: P[v][g] = dot(emb[v], W_ih[g]) + b_ih[g] + b_hh[g]
__device__ float g_P[(size_t)VOCAB * GATES];

// ---------------------------------------------------------------------------
// Kernel 1: P = emb @ W_ih^T + b  (unchanged, known-correct; ~FFMA bound)
// ---------------------------------------------------------------------------
__global__ __launch_bounds__(256) void proj_kernel(
    const float* __restrict__ emb,
    const float* __restrict__ W_ih,
    const float* __restrict__ b_ih,
    const float* __restrict__ b_hh)
{
    extern __shared__ float sm1[];
    float* As = sm1;              // [64][129]
    float* Bs = sm1 + 64 * 129;   // [64][129]

    const int tid  = threadIdx.x;
    const int tx   = tid & 15;
    const int ty   = tid >> 4;
    const int row0 = blockIdx.y << 6;
    const int n0   = blockIdx.x << 6;

    #pragma unroll
    for (int i = 0; i < 8; ++i) {
        int idx = tid + (i << 8);
        int m   = idx >> 5;
        int k4  = (idx & 31) << 2;
        int gm  = row0 + m;
        float4 a = make_float4(0.f, 0.f, 0.f, 0.f);
        if (gm < VOCAB)
            a = *reinterpret_cast<const float4*>(emb + (size_t)gm * DIM + k4);
        As[m * 129 + k4 + 0] = a.x;
        As[m * 129 + k4 + 1] = a.y;
        As[m * 129 + k4 + 2] = a.z;
        As[m * 129 + k4 + 3] = a.w;
        float4 w = *reinterpret_cast<const float4*>(W_ih + (size_t)(n0 + m) * DIM + k4);
        Bs[m * 129 + k4 + 0] = w.x;
        Bs[m * 129 + k4 + 1] = w.y;
        Bs[m * 129 + k4 + 2] = w.z;
        Bs[m * 129 + k4 + 3] = w.w;
    }
    __syncthreads();

    float acc[4][4];
    #pragma unroll
    for (int i = 0; i < 4; ++i)
        #pragma unroll
        for (int jj = 0; jj < 4; ++jj) acc[i][jj] = 0.f;

    const float* ap = As + (ty << 2) * 129;
    const float* bp = Bs + (tx << 2) * 129;

    #pragma unroll 8
    for (int k = 0; k < 128; ++k) {
        float a0 = ap[k], a1 = ap[k + 129], a2 = ap[k + 258], a3 = ap[k + 387];
        float b0 = bp[k], b1 = bp[k + 129], b2 = bp[k + 258], b3 = bp[k + 387];
        acc[0][0] += a0 * b0; acc[0][1] += a0 * b1; acc[0][2] += a0 * b2; acc[0][3] += a0 * b3;
        acc[1][0] += a1 * b0; acc[1][1] += a1 * b1; acc[1][2] += a1 * b2; acc[1][3] += a1 * b3;
        acc[2][0] += a2 * b0; acc[2][1] += a2 * b1; acc[2][2] += a2 * b2; acc[2][3] += a2 * b3;
        acc[3][0] += a3 * b0; acc[3][1] += a3 * b1; acc[3][2] += a3 * b2; acc[3][3] += a3 * b3;
    }

    int gn = n0 + (tx << 2);
    float bb0 = b_ih[gn + 0] + b_hh[gn + 0];
    float bb1 = b_ih[gn + 1] + b_hh[gn + 1];
    float bb2 = b_ih[gn + 2] + b_hh[gn + 2];
    float bb3 = b_ih[gn + 3] + b_hh[gn + 3];

    #pragma unroll
    for (int i = 0; i < 4; ++i) {
        int gm = row0 + (ty << 2) + i;
        if (gm < VOCAB) {
            float4 o = make_float4(acc[i][0] + bb0, acc[i][1] + bb1,
                                   acc[i][2] + bb2, acc[i][3] + bb3);
            *reinterpret_cast<float4*>(g_P + (size_t)gm * GATES + gn) = o;
        }
    }
}

// ---------------------------------------------------------------------------
// Kernel 2: recurrent LSTM, cluster-of-2 k-split.
//   cluster = 2 CTAs per batch element; rank r owns k in [64r, 64r+64).
//   All weights register-resident (32 ull/thread). Per step: half-K matial
//   matvec -> single DSMEM hop exchanging 512 partials each way (st.async +
//   mbarrier complete_tx, double-buffered) -> both ranks compute the gate /
//   c / h tail redundantly. Only ONE cross-SM latency per step.
// ---------------------------------------------------------------------------
#define FMA2(acc, a, b) \
    asm("fma.rn.f32x2 %0, %1, %2, %0;" : "+l"(acc) : "l"(a), "l"(b))

__device__ __forceinline__ float sig_f(float x) {
    return __fdividef(1.f, 1.f + __expf(-x));
}
__device__ __forceinline__ float tanh_f(float x) {
    float e = __expf(fminf(-2.f * x, 30.f));   // clamp: avoid inf -> NaN
    return __fdividef(1.f - e, 1.f + e);
}

__device__ __forceinline__ unsigned cvta_smem(const void* p) {
    unsigned r;
    asm("{ .reg .u64 t; cvta.to.shared.u64 t, %1; cvt.u32.u64 %0, t; }"
        : "=r"(r) : "l"(p));
    return r;
}

__global__ __launch_bounds__(512, 1) __cluster_dims__(2, 1, 1)
void lstm_kernel(
    const int*   __restrict__ tokens,
    const float* __restrict__ W_hh,
    float*       __restrict__ out)
{
    __shared__ __align__(16) unsigned long long mbar[1];
    __shared__ __align__(16) float h_s[128];
    __shared__ __align__(16) float a_s[512];
    __shared__ __align__(16) float pbuf[2][512];   // peer partials, double buffered
    __shared__ int tok_s[SEQ];

    const int j    = threadIdx.x;
    const int b    = blockIdx.x >> 1;
    const int rank = blockIdx.x & 1;
    const int peer = rank ^ 1;

    const unsigned long long* W64 = (const unsigned long long*)W_hh;

    // Register-resident weight half: W_hh[j][64*rank .. 64*rank+63]
    unsigned long long wreg[32];
    #pragma unroll
    for (int kk = 0; kk < 32; ++kk)
        wreg[kk] = W64[(size_t)j * 64 + (rank << 5) + kk];

    if (rank == 0) {
        for (int idx = j; idx < SEQ; idx += 512)
            tok_s[idx] = tokens[(size_t)b * SEQ + idx];
    }
    if (j < 128) h_s[j] = 0.f;

    const unsigned mbar_a = cvta_smem(mbar);
    const unsigned pbuf_a = cvta_smem(pbuf);
    if (j == 0) {
        asm volatile("mbarrier.init.shared.b64 [%0], %1;"
                     :: "r"(mbar_a), "r"(1u) : "memory");
    }
    __syncthreads();
    // peer mbarriers must be live before any st.async targets them
    asm volatile("barrier.cluster.arrive.aligned;" ::: "memory");
    asm volatile("barrier.cluster.wait.aligned;"   ::: "memory");

    // remote (peer-CTA) addresses, loop-invariant
    unsigned rm_mbar, rm_pbuf;
    asm("mapa.shared::cluster.u32 %0, %1, %2;" : "=r"(rm_mbar) : "r"(mbar_a), "r"(peer));
    asm("mapa.shared::cluster.u32 %0, %1, %2;" : "=r"(rm_pbuf) : "r"(pbuf_a), "r"(peer));

    const float* Pp = (const float*)g_P;
    float x_cur = (rank == 0) ? __ldg(Pp + (size_t)tok_s[0] * GATES + j) : 0.f;
    float c = 0.f;
    const bool sel_tanh = ((j >> 7) == 2);   // gate order i, f, g(tanh), o
    const ulonglong2* h2 = (const ulonglong2*)(h_s + (rank << 6));

    for (int t = 0; t < SEQ; ++t) {
        // arm this phase: 1 arrival + 2048 tx bytes (512 x 4B from peer)
        if (j == 0) {
            asm volatile("mbarrier.arrive.expect_tx.shared.b64 _, [%0], %1;"
                         :: "r"(mbar_a), "r"(2048u) : "memory");
        }

        float xg = x_cur;
        if (rank == 0 && t + 1 < SEQ)
            x_cur = __ldg(Pp + (size_t)tok_s[t + 1] * GATES + j);

        // half-K matvec, 4 independent accumulation chains
        unsigned long long acc0 = 0ull, acc1 = 0ull, acc2 = 0ull, acc3 = 0ull;
        #pragma unroll
        for (int q = 0; q < 8; ++q) {
            ulonglong2 ha = h2[2 * q];       // broadcast LDS.128
            ulonglong2 hb = h2[2 * q + 1];
            FMA2(acc0, wreg[4 * q + 0], ha.x);
            FMA2(acc1, wreg[4 * q + 1], ha.y);
            FMA2(acc2, wreg[4 * q + 2], hb.x);
            FMA2(acc3, wreg[4 * q + 3], hb.y);
        }
        float s0, s1, s2, s3, s4, s5, s6, s7;
        asm("mov.b64 {%0,%1}, %2;" : "=f"(s0), "=f"(s1) : "l"(acc0));
        asm("mov.b64 {%0,%1}, %2;" : "=f"(s2), "=f"(s3) : "l"(acc1));
        asm("mov.b64 {%0,%1}, %2;" : "=f"(s4), "=f"(s5) : "l"(acc2));
        asm("mov.b64 {%0,%1}, %2;" : "=f"(s6), "=f"(s7) : "l"(acc3));
        float part = ((s0 + s1) + (s2 + s3)) + ((s4 + s5) + (s6 + s7));
        if (rank == 0) part += xg;           // fold xg into rank0's partial

        // ship my partial to the peer's pbuf[t&1][j]; complete_tx on peer mbar
        {
            unsigned dst = rm_pbuf + (((t & 1) << 9) + j) * 4u;
            asm volatile(
                "st.async.shared::cluster.mbarrier::complete_tx::bytes.b32 [%0], %1, [%2];"
                :: "r"(dst), "r"(__float_as_uint(part)), "r"(rm_mbar) : "memory");
        }

        // wait for peer's 512 partials (phase parity t&1)
        {
            unsigned done;
            asm volatile(
                "{\n\t.reg .pred p;\n\t"
                "mbarrier.try_wait.parity.acquire.cta.shared::cta.b64 p, [%1], %2;\n\t"
                "selp.b32 %0, 1, 0, p;\n\t}"
                : "=r"(done) : "r"(mbar_a), "r"((unsigned)(t & 1)) : "memory");
            if (!done) {
                asm volatile(
                    "{\n\t.reg .pred P1;\n\t"
                    "WL_%=:\n\t"
                    "mbarrier.try_wait.parity.acquire.cta.shared::cta.b64 P1, [%0], %1, 0x989680;\n\t"
                    "@P1 bra.uni WD_%=;\n\t"
                    "bra.uni WL_%=;\n\t"
                    "WD_%=:\n\t}"
                    :: "r"(mbar_a), "r"((unsigned)(t & 1)) : "memory");
            }
        }

        float g = part + pbuf[t & 1][j];
        float act = sel_tanh ? tanh_f(g) : sig_f(g);
        a_s[j] = act;
        __syncthreads();

        if (j < 128) {   // redundant tail on both ranks (keeps c, h local)
            float ai = a_s[j], af = a_s[128 + j], ag = a_s[256 + j], ao = a_s[384 + j];
            c = fmaf(af, c, ai * ag);
            h_s[j] = ao * tanh_f(c);
        }
        __syncthreads();
    }

    if (rank == 0 && j < 128) {
        out[(size_t)b * HID + j] = h_s[j];                        // h  [1,64,128]
        out[(size_t)BATCH * HID + (size_t)b * HID + j] = c;       // c  [1,64,128]
    }

    // no CTA may exit while its outbound DSMEM stores could be in flight
    asm volatile("barrier.cluster.arrive.aligned;" ::: "memory");
    asm volatile("barrier.cluster.wait.aligned;"   ::: "memory");
}

// ---------------------------------------------------------------------------
extern "C" void kernel_launch(void* const* d_in, const int* in_sizes, int n_in,
                              void* d_out, int out_size)
{
    const int*   tokens = (const int*)  d_in[0];
    const float* emb    = (const float*)d_in[1];
    const float* W_ih   = (const float*)d_in[2];
    const float* W_hh   = (const float*)d_in[3];
    const float* b_ih   = (const float*)d_in[4];
    const float* b_hh   = (const float*)d_in[5];
    float* out = (float*)d_out;

    const int smem1 = 2 * 64 * 129 * (int)sizeof(float);   // 66048 B
    cudaFuncSetAttribute(proj_kernel, cudaFuncAttributeMaxDynamicSharedMemorySize, smem1);

    dim3 g1(GATES / 64, (VOCAB + 63) / 64);
    proj_kernel<<<g1, 256, smem1>>>(emb, W_ih, b_ih, b_hh);
    lstm_kernel<<<BATCH * 2, 512>>>(tokens, W_hh, out);
}